// round 7
// baseline (speedup 1.0000x reference)
#include <cuda_runtime.h>
#include <stdint.h>

// ROISelect: per-row top-k(score) + ROI gather, monolithic, sort-free.
// One CTA per row: float4 streaming scan filters score >= 2.72 (~427
// candidates/row, 8.3-sigma margin) into shared memory, then exact sorted
// ranks via CTA-wide parallel all-pairs comparison (count x SPLIT partial-rank
// tasks accumulated with smem atomics) over unique u64 keys (value | ~index,
// matching tf.nn.top_k tie order), then a short emit pass writes out[rank].
// Exact 12-bit radix-select fallback guarantees correctness if the threshold
// ever misfires (count outside [256, 4096]).

#define B_ROWS 128
#define N_COLS 131072
#define K_TOP  256
#define TPB    1024
#define CAP    4096
#define V4_PER_THREAD (N_COLS / 4 / TPB)   // 32
#define GROUPS 8
#define GSIZE  (V4_PER_THREAD / GROUPS)    // 4 float4 per load group
#define SPLIT  8                           // partial-rank segments per candidate

__device__ __forceinline__ unsigned int f2u(float f) {
    unsigned int b = __float_as_uint(f);
    return (b & 0x80000000u) ? ~b : (b | 0x80000000u);
}
__device__ __forceinline__ float u2f(unsigned int u) {
    unsigned int b = (u & 0x80000000u) ? (u ^ 0x80000000u) : ~u;
    return __uint_as_float(b);
}

__global__ __launch_bounds__(TPB, 1)
void roiselect_kernel(const float* __restrict__ score,
                      const float* __restrict__ roi,
                      float* __restrict__ out_roi,
                      float* __restrict__ out_score)
{
    __shared__ int s_cnt;
    __shared__ int s_bin;
    // Dynamic smem: cand[CAP] (32 KB) then s_rank[CAP] (16 KB).
    extern __shared__ unsigned long long cand[];
    unsigned int* s_rank = (unsigned int*)(cand + CAP);

    const int tid = threadIdx.x;
    const int row = blockIdx.x;
    const float4* sc4 = (const float4*)(score + (size_t)row * N_COLS);

    if (tid == 0) s_cnt = 0;
    __syncthreads();

    // ---------- Streaming filter: groups of 4 batched LDG.128 ----------
    const float TGUESS = 2.72f;
    #pragma unroll
    for (int g = 0; g < GROUPS; ++g) {
        float4 v[GSIZE];
        #pragma unroll
        for (int u = 0; u < GSIZE; ++u)
            v[u] = sc4[tid + (g * GSIZE + u) * TPB];
        #pragma unroll
        for (int u = 0; u < GSIZE; ++u) {
            int ebase = (tid + (g * GSIZE + u) * TPB) * 4;
            float vals[4] = {v[u].x, v[u].y, v[u].z, v[u].w};
            #pragma unroll
            for (int c = 0; c < 4; ++c) {
                if (vals[c] >= TGUESS) {
                    int pos = atomicAdd(&s_cnt, 1);
                    if (pos < CAP) {
                        unsigned int uu = __float_as_uint(vals[c]) | 0x80000000u;
                        cand[pos] = ((unsigned long long)uu << 32)
                                  | (unsigned int)~(unsigned int)(ebase + c);
                    }
                }
            }
        }
    }
    __syncthreads();
    unsigned int count = (unsigned int)s_cnt;

    // ---------- Exact fallback: 12-bit radix select (never taken on this data) ----------
    if (count < K_TOP || count > CAP) {
        unsigned int* hist  = (unsigned int*)cand;   // 4096 bins (aliased)
        unsigned int* sdata = hist + 4096;           // 1024 thread sums
        for (int i = tid; i < 4096; i += TPB) hist[i] = 0;
        if (tid == 0) s_cnt = 0;
        __syncthreads();

        for (int i = 0; i < V4_PER_THREAD; ++i) {
            float4 f = sc4[tid + i * TPB];
            float vals[4] = {f.x, f.y, f.z, f.w};
            #pragma unroll
            for (int c = 0; c < 4; ++c)
                atomicAdd(&hist[f2u(vals[c]) >> 20], 1u);
        }
        __syncthreads();

        unsigned int h0 = hist[4*tid+0], h1 = hist[4*tid+1];
        unsigned int h2 = hist[4*tid+2], h3 = hist[4*tid+3];
        sdata[tid] = h0 + h1 + h2 + h3;
        __syncthreads();
        for (int d = 1; d < TPB; d <<= 1) {          // inclusive suffix scan
            unsigned int vv = (tid + d < TPB) ? sdata[tid + d] : 0u;
            __syncthreads();
            sdata[tid] += vv;
            __syncthreads();
        }
        unsigned int Anext = (tid + 1 < TPB) ? sdata[tid + 1] : 0u;
        unsigned int cum3 = Anext + h3;
        unsigned int cum2 = cum3 + h2;
        unsigned int cum1 = cum2 + h1;
        unsigned int cum0 = cum1 + h0;
        if (cum3 >= K_TOP && Anext < K_TOP) s_bin = 4*tid + 3;
        if (cum2 >= K_TOP && cum3  < K_TOP) s_bin = 4*tid + 2;
        if (cum1 >= K_TOP && cum2  < K_TOP) s_bin = 4*tid + 1;
        if (cum0 >= K_TOP && cum1  < K_TOP) s_bin = 4*tid + 0;
        __syncthreads();
        unsigned int uthr = (unsigned int)s_bin << 20;
        __syncthreads();   // uthr read by all; hist region can be overwritten

        for (int i = 0; i < V4_PER_THREAD; ++i) {
            int v4i = tid + i * TPB;
            float4 f = sc4[v4i];
            int ebase = v4i * 4;
            float vals[4] = {f.x, f.y, f.z, f.w};
            #pragma unroll
            for (int c = 0; c < 4; ++c) {
                unsigned int u = f2u(vals[c]);
                if (u >= uthr) {
                    int pos = atomicAdd(&s_cnt, 1);
                    if (pos < CAP)
                        cand[pos] = ((unsigned long long)u << 32)
                                  | (unsigned int)~(unsigned int)(ebase + c);
                }
            }
        }
        __syncthreads();
        count = min((unsigned int)s_cnt, (unsigned int)CAP);
    }

    // Pad to even for the ulonglong2 loop (a 0 key never outranks a real key:
    // all real keys have bit 63 set), and zero the rank accumulators.
    if (tid == 0 && (count & 1u)) cand[count] = 0ULL;
    for (unsigned int i = tid; i < count; i += TPB) s_rank[i] = 0u;
    __syncthreads();

    const int half  = (int)((count + 1u) >> 1);          // ulonglong2 pairs
    const int chunk = (half + SPLIT - 1) / SPLIT;        // pairs per segment
    const ulonglong2* c2 = (const ulonglong2*)cand;

    // ---------- CTA-wide parallel rank: count*SPLIT partial-rank tasks ----------
    const int ntasks = (int)count * SPLIT;
    for (int task = tid; task < ntasks; task += TPB) {
        const int c   = task >> 3;                       // task / SPLIT
        const int seg = task & (SPLIT - 1);
        const int i0  = seg * chunk;
        const int i1  = min(i0 + chunk, half);
        const unsigned long long key = cand[c];
        int partial = 0;
        for (int i = i0; i < i1; ++i) {
            ulonglong2 p = c2[i];
            partial += (p.x > key) + (p.y > key);
        }
        if (partial) atomicAdd(&s_rank[c], (unsigned int)partial);
    }
    __syncthreads();

    // ---------- Emit top-256: sorted scores + ROI gather ----------
    for (int c = tid; c < (int)count; c += TPB) {
        unsigned int rank = s_rank[c];
        if (rank < K_TOP) {
            unsigned long long key = cand[c];
            unsigned int u   = (unsigned int)(key >> 32);
            unsigned int idx = ~(unsigned int)key;
            const float4* r4 = (const float4*)roi;
            float4 rv = r4[(size_t)row * N_COLS + idx];  // issue gather first
            out_score[row * K_TOP + rank] = u2f(u);
            ((float4*)out_roi)[row * K_TOP + rank] = rv;
        }
    }
}

extern "C" void kernel_launch(void* const* d_in, const int* in_sizes, int n_in,
                              void* d_out, int out_size) {
    (void)in_sizes; (void)n_in; (void)out_size;
    const float* score = (const float*)d_in[0];
    const float* roi   = (const float*)d_in[1];
    float* out_roi   = (float*)d_out;                               // [128,256,4]
    float* out_score = (float*)d_out + (size_t)B_ROWS * K_TOP * 4;  // [128,256]
    const int smem = CAP * sizeof(unsigned long long)               // cand
                   + CAP * sizeof(unsigned int);                    // s_rank
    cudaFuncSetAttribute(roiselect_kernel,
                         cudaFuncAttributeMaxDynamicSharedMemorySize, smem);
    roiselect_kernel<<<B_ROWS, TPB, smem>>>(score, roi, out_roi, out_score);
}

// round 8
// speedup vs baseline: 2.1405x; 2.1405x over previous
#include <cuda_runtime.h>
#include <stdint.h>

// ROISelect: per-row top-k(score) + ROI gather, monolithic, sort-free.
// One CTA per row: float4 streaming scan filters score >= 2.72 (~427
// candidates/row, 8.3-sigma margin) into shared memory, then exact sorted
// ranks via warp-cooperative all-pairs comparison (one warp per candidate,
// lanes split the comparison array, REDUX sum) over unique u64 keys
// (value | ~index, matching tf.nn.top_k tie order). Lane 0 emits out[rank].
// Exact 12-bit radix-select fallback guarantees correctness if the threshold
// ever misfires (count outside [256, 4096]).

#define B_ROWS 128
#define N_COLS 131072
#define K_TOP  256
#define TPB    1024
#define CAP    4096
#define V4_PER_THREAD (N_COLS / 4 / TPB)   // 32
#define GROUPS 8
#define GSIZE  (V4_PER_THREAD / GROUPS)    // 4 float4 per load group

__device__ __forceinline__ unsigned int f2u(float f) {
    unsigned int b = __float_as_uint(f);
    return (b & 0x80000000u) ? ~b : (b | 0x80000000u);
}
__device__ __forceinline__ float u2f(unsigned int u) {
    unsigned int b = (u & 0x80000000u) ? (u ^ 0x80000000u) : ~u;
    return __uint_as_float(b);
}

__global__ __launch_bounds__(TPB, 1)
void roiselect_kernel(const float* __restrict__ score,
                      const float* __restrict__ roi,
                      float* __restrict__ out_roi,
                      float* __restrict__ out_score)
{
    __shared__ int s_cnt;
    __shared__ int s_bin;
    extern __shared__ unsigned long long cand[];   // CAP entries = 32 KB

    const int tid = threadIdx.x;
    const int row = blockIdx.x;
    const float4* sc4 = (const float4*)(score + (size_t)row * N_COLS);

    if (tid == 0) s_cnt = 0;
    __syncthreads();

    // ---------- Streaming filter: groups of 4 batched LDG.128 ----------
    const float TGUESS = 2.72f;
    #pragma unroll
    for (int g = 0; g < GROUPS; ++g) {
        float4 v[GSIZE];
        #pragma unroll
        for (int u = 0; u < GSIZE; ++u)
            v[u] = sc4[tid + (g * GSIZE + u) * TPB];
        #pragma unroll
        for (int u = 0; u < GSIZE; ++u) {
            int ebase = (tid + (g * GSIZE + u) * TPB) * 4;
            float vals[4] = {v[u].x, v[u].y, v[u].z, v[u].w};
            #pragma unroll
            for (int c = 0; c < 4; ++c) {
                if (vals[c] >= TGUESS) {
                    int pos = atomicAdd(&s_cnt, 1);
                    if (pos < CAP) {
                        unsigned int uu = __float_as_uint(vals[c]) | 0x80000000u;
                        cand[pos] = ((unsigned long long)uu << 32)
                                  | (unsigned int)~(unsigned int)(ebase + c);
                    }
                }
            }
        }
    }
    __syncthreads();
    unsigned int count = (unsigned int)s_cnt;

    // ---------- Exact fallback: 12-bit radix select (never taken on this data) ----------
    if (count < K_TOP || count > CAP) {
        unsigned int* hist  = (unsigned int*)cand;   // 4096 bins (aliased)
        unsigned int* sdata = hist + 4096;           // 1024 thread sums
        for (int i = tid; i < 4096; i += TPB) hist[i] = 0;
        if (tid == 0) s_cnt = 0;
        __syncthreads();

        for (int i = 0; i < V4_PER_THREAD; ++i) {
            float4 f = sc4[tid + i * TPB];
            float vals[4] = {f.x, f.y, f.z, f.w};
            #pragma unroll
            for (int c = 0; c < 4; ++c)
                atomicAdd(&hist[f2u(vals[c]) >> 20], 1u);
        }
        __syncthreads();

        unsigned int h0 = hist[4*tid+0], h1 = hist[4*tid+1];
        unsigned int h2 = hist[4*tid+2], h3 = hist[4*tid+3];
        sdata[tid] = h0 + h1 + h2 + h3;
        __syncthreads();
        for (int d = 1; d < TPB; d <<= 1) {          // inclusive suffix scan
            unsigned int vv = (tid + d < TPB) ? sdata[tid + d] : 0u;
            __syncthreads();
            sdata[tid] += vv;
            __syncthreads();
        }
        unsigned int Anext = (tid + 1 < TPB) ? sdata[tid + 1] : 0u;
        unsigned int cum3 = Anext + h3;
        unsigned int cum2 = cum3 + h2;
        unsigned int cum1 = cum2 + h1;
        unsigned int cum0 = cum1 + h0;
        if (cum3 >= K_TOP && Anext < K_TOP) s_bin = 4*tid + 3;
        if (cum2 >= K_TOP && cum3  < K_TOP) s_bin = 4*tid + 2;
        if (cum1 >= K_TOP && cum2  < K_TOP) s_bin = 4*tid + 1;
        if (cum0 >= K_TOP && cum1  < K_TOP) s_bin = 4*tid + 0;
        __syncthreads();
        unsigned int uthr = (unsigned int)s_bin << 20;
        __syncthreads();   // uthr read by all; hist region can be overwritten

        for (int i = 0; i < V4_PER_THREAD; ++i) {
            int v4i = tid + i * TPB;
            float4 f = sc4[v4i];
            int ebase = v4i * 4;
            float vals[4] = {f.x, f.y, f.z, f.w};
            #pragma unroll
            for (int c = 0; c < 4; ++c) {
                unsigned int u = f2u(vals[c]);
                if (u >= uthr) {
                    int pos = atomicAdd(&s_cnt, 1);
                    if (pos < CAP)
                        cand[pos] = ((unsigned long long)u << 32)
                                  | (unsigned int)~(unsigned int)(ebase + c);
                }
            }
        }
        __syncthreads();
        count = min((unsigned int)s_cnt, (unsigned int)CAP);
    }
    __syncthreads();

    // ---------- Warp-cooperative rank: one warp per candidate ----------
    // Lanes split the comparison array; REDUX sums partial ranks. Keys are
    // unique (index tie-break), so rank is an exact permutation of [0,count).
    const int wid  = tid >> 5;
    const int lane = tid & 31;
    for (int c = wid; c < (int)count; c += (TPB / 32)) {
        const unsigned long long key = cand[c];
        unsigned int partial = 0;
        #pragma unroll 4
        for (unsigned int i = lane; i < count; i += 32)
            partial += (cand[i] > key);
        unsigned int rank = __reduce_add_sync(0xffffffffu, partial);
        if (lane == 0 && rank < K_TOP) {
            unsigned int u   = (unsigned int)(key >> 32);
            unsigned int idx = ~(unsigned int)key;
            const float4* r4 = (const float4*)roi;
            float4 rv = r4[(size_t)row * N_COLS + idx];
            out_score[row * K_TOP + rank] = u2f(u);
            ((float4*)out_roi)[row * K_TOP + rank] = rv;
        }
    }
}

extern "C" void kernel_launch(void* const* d_in, const int* in_sizes, int n_in,
                              void* d_out, int out_size) {
    (void)in_sizes; (void)n_in; (void)out_size;
    const float* score = (const float*)d_in[0];
    const float* roi   = (const float*)d_in[1];
    float* out_roi   = (float*)d_out;                               // [128,256,4]
    float* out_score = (float*)d_out + (size_t)B_ROWS * K_TOP * 4;  // [128,256]
    roiselect_kernel<<<B_ROWS, TPB, CAP * sizeof(unsigned long long)>>>(
        score, roi, out_roi, out_score);
}

// round 9
// speedup vs baseline: 2.3496x; 1.0977x over previous
#include <cuda_runtime.h>
#include <stdint.h>

// ROISelect: per-row top-k(score) + ROI gather, monolithic, sort-free.
// One CTA (512 threads) per row: float4 streaming scan (8 groups of 8
// batched LDG.128/thread) filters score >= 2.72 (~427 candidates/row,
// 8.3-sigma margin) into shared memory, then exact sorted ranks via
// per-thread all-pairs comparison over unique u64 keys (value | ~index,
// matching tf.nn.top_k tie order), writing out[rank] directly.
// TPB=512 (not 1024) so each thread gets a 128-register budget — the
// 64-reg cap at TPB=1024 forced local-memory spills in the rank loop.
// Exact 12-bit radix-select fallback guarantees correctness if the
// threshold ever misfires (count outside [256, 4096]).

#define B_ROWS 128
#define N_COLS 131072
#define K_TOP  256
#define TPB    512
#define CAP    4096
#define V4_PER_THREAD (N_COLS / 4 / TPB)   // 64
#define GROUPS 8
#define GSIZE  (V4_PER_THREAD / GROUPS)    // 8 float4 per load group

__device__ __forceinline__ unsigned int f2u(float f) {
    unsigned int b = __float_as_uint(f);
    return (b & 0x80000000u) ? ~b : (b | 0x80000000u);
}
__device__ __forceinline__ float u2f(unsigned int u) {
    unsigned int b = (u & 0x80000000u) ? (u ^ 0x80000000u) : ~u;
    return __uint_as_float(b);
}

__global__ __launch_bounds__(TPB, 1)
void roiselect_kernel(const float* __restrict__ score,
                      const float* __restrict__ roi,
                      float* __restrict__ out_roi,
                      float* __restrict__ out_score)
{
    __shared__ int s_cnt;
    __shared__ int s_bin;
    extern __shared__ unsigned long long cand[];   // CAP entries = 32 KB

    const int tid = threadIdx.x;
    const int row = blockIdx.x;
    const float4* sc4 = (const float4*)(score + (size_t)row * N_COLS);

    if (tid == 0) s_cnt = 0;
    __syncthreads();

    // ---------- Streaming filter: groups of 8 batched LDG.128 ----------
    const float TGUESS = 2.72f;
    #pragma unroll
    for (int g = 0; g < GROUPS; ++g) {
        float4 v[GSIZE];
        #pragma unroll
        for (int u = 0; u < GSIZE; ++u)
            v[u] = sc4[tid + (g * GSIZE + u) * TPB];
        #pragma unroll
        for (int u = 0; u < GSIZE; ++u) {
            int ebase = (tid + (g * GSIZE + u) * TPB) * 4;
            float vals[4] = {v[u].x, v[u].y, v[u].z, v[u].w};
            #pragma unroll
            for (int c = 0; c < 4; ++c) {
                if (vals[c] >= TGUESS) {
                    int pos = atomicAdd(&s_cnt, 1);
                    if (pos < CAP) {
                        unsigned int uu = __float_as_uint(vals[c]) | 0x80000000u;
                        cand[pos] = ((unsigned long long)uu << 32)
                                  | (unsigned int)~(unsigned int)(ebase + c);
                    }
                }
            }
        }
    }
    __syncthreads();
    unsigned int count = (unsigned int)s_cnt;

    // ---------- Exact fallback: 12-bit radix select (never taken on this data) ----------
    if (count < K_TOP || count > CAP) {
        unsigned int* hist  = (unsigned int*)cand;   // 4096 bins (aliased)
        unsigned int* sdata = hist + 4096;           // TPB thread sums
        for (int i = tid; i < 4096; i += TPB) hist[i] = 0;
        if (tid == 0) s_cnt = 0;
        __syncthreads();

        for (int i = 0; i < V4_PER_THREAD; ++i) {
            float4 f = sc4[tid + i * TPB];
            float vals[4] = {f.x, f.y, f.z, f.w};
            #pragma unroll
            for (int c = 0; c < 4; ++c)
                atomicAdd(&hist[f2u(vals[c]) >> 20], 1u);
        }
        __syncthreads();

        // Each thread owns 8 consecutive bins; suffix-scan thread totals.
        unsigned int h[8];
        unsigned int tsum = 0;
        #pragma unroll
        for (int b = 0; b < 8; ++b) { h[b] = hist[8*tid + b]; tsum += h[b]; }
        sdata[tid] = tsum;
        __syncthreads();
        for (int d = 1; d < TPB; d <<= 1) {          // inclusive suffix scan
            unsigned int vv = (tid + d < TPB) ? sdata[tid + d] : 0u;
            __syncthreads();
            sdata[tid] += vv;
            __syncthreads();
        }
        unsigned int cum = (tid + 1 < TPB) ? sdata[tid + 1] : 0u;  // suffix after my bins
        // Walk my 8 bins from highest to lowest, find the K_TOP crossing.
        #pragma unroll
        for (int b = 7; b >= 0; --b) {
            unsigned int nc = cum + h[b];
            if (nc >= K_TOP && cum < K_TOP) s_bin = 8*tid + b;
            cum = nc;
        }
        __syncthreads();
        unsigned int uthr = (unsigned int)s_bin << 20;
        __syncthreads();   // uthr read by all; hist region can be overwritten

        for (int i = 0; i < V4_PER_THREAD; ++i) {
            int v4i = tid + i * TPB;
            float4 f = sc4[v4i];
            int ebase = v4i * 4;
            float vals[4] = {f.x, f.y, f.z, f.w};
            #pragma unroll
            for (int c = 0; c < 4; ++c) {
                unsigned int u = f2u(vals[c]);
                if (u >= uthr) {
                    int pos = atomicAdd(&s_cnt, 1);
                    if (pos < CAP)
                        cand[pos] = ((unsigned long long)u << 32)
                                  | (unsigned int)~(unsigned int)(ebase + c);
                }
            }
        }
        __syncthreads();
        count = min((unsigned int)s_cnt, (unsigned int)CAP);
    }

    // Pad to even for the ulonglong2 inner loop (a 0 key never outranks a
    // real key: all real keys have bit 63 set). count==CAP is even, so the
    // pad write never exceeds the buffer.
    if (tid == 0 && (count & 1u)) cand[count] = 0ULL;
    __syncthreads();
    const int half = (int)((count + 1u) >> 1);
    const ulonglong2* c2 = (const ulonglong2*)cand;

    // ---------- Exact rank selection (keys unique via index tie-break) ----------
    for (int c = tid; c < (int)count; c += TPB) {
        unsigned long long key = cand[c];
        int rank = 0;
        #pragma unroll 8
        for (int i = 0; i < half; ++i) {
            ulonglong2 p = c2[i];
            rank += (p.x > key) + (p.y > key);
        }
        if (rank < K_TOP) {
            unsigned int u   = (unsigned int)(key >> 32);
            unsigned int idx = ~(unsigned int)key;
            const float4* r4 = (const float4*)roi;
            float4 rv = r4[(size_t)row * N_COLS + idx];
            out_score[row * K_TOP + rank] = u2f(u);
            ((float4*)out_roi)[row * K_TOP + rank] = rv;
        }
    }
}

extern "C" void kernel_launch(void* const* d_in, const int* in_sizes, int n_in,
                              void* d_out, int out_size) {
    (void)in_sizes; (void)n_in; (void)out_size;
    const float* score = (const float*)d_in[0];
    const float* roi   = (const float*)d_in[1];
    float* out_roi   = (float*)d_out;                               // [128,256,4]
    float* out_score = (float*)d_out + (size_t)B_ROWS * K_TOP * 4;  // [128,256]
    roiselect_kernel<<<B_ROWS, TPB, CAP * sizeof(unsigned long long)>>>(
        score, roi, out_roi, out_score);
}

// round 10
// speedup vs baseline: 2.8713x; 1.2220x over previous
#include <cuda_runtime.h>
#include <stdint.h>

// ROISelect: per-row top-k(score) + ROI gather, monolithic, sort-free.
// One CTA (1024 thr) per row: float4 streaming scan filters score >= 2.80
// (~335 candidates/row, 4.3-sigma margin above k=256) into shared memory,
// then exact sorted ranks via all-pairs comparison over unique u64 keys
// (value | ~index, matching tf.nn.top_k tie order). The rank of candidate c
// is computed by TWO threads (t and t+512), each scanning half the candidate
// array, combined through a small shared buffer — halving the latency-bound
// serial comparison chain. Exact 12-bit radix-select fallback guarantees
// correctness if the threshold ever misfires (count outside [256, 4096]).

#define B_ROWS 128
#define N_COLS 131072
#define K_TOP  256
#define TPB    1024
#define CAP    4096
#define V4_PER_THREAD (N_COLS / 4 / TPB)   // 32
#define GROUPS 8
#define GSIZE  (V4_PER_THREAD / GROUPS)    // 4 float4 per load group

__device__ __forceinline__ unsigned int f2u(float f) {
    unsigned int b = __float_as_uint(f);
    return (b & 0x80000000u) ? ~b : (b | 0x80000000u);
}
__device__ __forceinline__ float u2f(unsigned int u) {
    unsigned int b = (u & 0x80000000u) ? (u ^ 0x80000000u) : ~u;
    return __uint_as_float(b);
}

__global__ __launch_bounds__(TPB, 1)
void roiselect_kernel(const float* __restrict__ score,
                      const float* __restrict__ roi,
                      float* __restrict__ out_roi,
                      float* __restrict__ out_score)
{
    __shared__ int s_cnt;
    __shared__ int s_bin;
    __shared__ unsigned int s_half[TPB];           // split-rank partials (4 KB)
    extern __shared__ unsigned long long cand[];   // CAP entries = 32 KB

    const int tid = threadIdx.x;
    const int row = blockIdx.x;
    const float4* sc4 = (const float4*)(score + (size_t)row * N_COLS);

    if (tid == 0) s_cnt = 0;
    __syncthreads();

    // ---------- Streaming filter: groups of 4 batched LDG.128 ----------
    const float TGUESS = 2.80f;
    #pragma unroll
    for (int g = 0; g < GROUPS; ++g) {
        float4 v[GSIZE];
        #pragma unroll
        for (int u = 0; u < GSIZE; ++u)
            v[u] = sc4[tid + (g * GSIZE + u) * TPB];
        #pragma unroll
        for (int u = 0; u < GSIZE; ++u) {
            int ebase = (tid + (g * GSIZE + u) * TPB) * 4;
            float vals[4] = {v[u].x, v[u].y, v[u].z, v[u].w};
            #pragma unroll
            for (int c = 0; c < 4; ++c) {
                if (vals[c] >= TGUESS) {
                    int pos = atomicAdd(&s_cnt, 1);
                    if (pos < CAP) {
                        unsigned int uu = __float_as_uint(vals[c]) | 0x80000000u;
                        cand[pos] = ((unsigned long long)uu << 32)
                                  | (unsigned int)~(unsigned int)(ebase + c);
                    }
                }
            }
        }
    }
    __syncthreads();
    unsigned int count = (unsigned int)s_cnt;

    // ---------- Exact fallback: 12-bit radix select (never taken on this data) ----------
    if (count < K_TOP || count > CAP) {
        unsigned int* hist  = (unsigned int*)cand;   // 4096 bins (aliased)
        unsigned int* sdata = hist + 4096;           // 1024 thread sums
        for (int i = tid; i < 4096; i += TPB) hist[i] = 0;
        if (tid == 0) s_cnt = 0;
        __syncthreads();

        for (int i = 0; i < V4_PER_THREAD; ++i) {
            float4 f = sc4[tid + i * TPB];
            float vals[4] = {f.x, f.y, f.z, f.w};
            #pragma unroll
            for (int c = 0; c < 4; ++c)
                atomicAdd(&hist[f2u(vals[c]) >> 20], 1u);
        }
        __syncthreads();

        unsigned int h0 = hist[4*tid+0], h1 = hist[4*tid+1];
        unsigned int h2 = hist[4*tid+2], h3 = hist[4*tid+3];
        sdata[tid] = h0 + h1 + h2 + h3;
        __syncthreads();
        for (int d = 1; d < TPB; d <<= 1) {          // inclusive suffix scan
            unsigned int vv = (tid + d < TPB) ? sdata[tid + d] : 0u;
            __syncthreads();
            sdata[tid] += vv;
            __syncthreads();
        }
        unsigned int Anext = (tid + 1 < TPB) ? sdata[tid + 1] : 0u;
        unsigned int cum3 = Anext + h3;
        unsigned int cum2 = cum3 + h2;
        unsigned int cum1 = cum2 + h1;
        unsigned int cum0 = cum1 + h0;
        if (cum3 >= K_TOP && Anext < K_TOP) s_bin = 4*tid + 3;
        if (cum2 >= K_TOP && cum3  < K_TOP) s_bin = 4*tid + 2;
        if (cum1 >= K_TOP && cum2  < K_TOP) s_bin = 4*tid + 1;
        if (cum0 >= K_TOP && cum1  < K_TOP) s_bin = 4*tid + 0;
        __syncthreads();
        unsigned int uthr = (unsigned int)s_bin << 20;
        __syncthreads();   // uthr read by all; hist region can be overwritten

        for (int i = 0; i < V4_PER_THREAD; ++i) {
            int v4i = tid + i * TPB;
            float4 f = sc4[v4i];
            int ebase = v4i * 4;
            float vals[4] = {f.x, f.y, f.z, f.w};
            #pragma unroll
            for (int c = 0; c < 4; ++c) {
                unsigned int u = f2u(vals[c]);
                if (u >= uthr) {
                    int pos = atomicAdd(&s_cnt, 1);
                    if (pos < CAP)
                        cand[pos] = ((unsigned long long)u << 32)
                                  | (unsigned int)~(unsigned int)(ebase + c);
                }
            }
        }
        __syncthreads();
        count = min((unsigned int)s_cnt, (unsigned int)CAP);
    }

    // Pad to even for the ulonglong2 loops (a 0 key never outranks a real
    // key: all real keys have bit 63 set). count==CAP is even, so the pad
    // write never exceeds the buffer.
    if (tid == 0 && (count & 1u)) cand[count] = 0ULL;
    __syncthreads();
    const int pairs = (int)((count + 1u) >> 1);
    const ulonglong2* c2 = (const ulonglong2*)cand;

    if (count <= 512) {
        // ---------- Split rank: 2 threads per candidate ----------
        const int t     = tid & 511;            // candidate id
        const int which = tid >> 9;             // 0 = low half, 1 = high half
        const int ph    = pairs >> 1;
        const int i0    = which ? ph : 0;
        const int i1    = which ? pairs : ph;
        unsigned int partial = 0;
        if (t < (int)count) {
            const unsigned long long key = cand[t];
            #pragma unroll 4
            for (int i = i0; i < i1; ++i) {
                ulonglong2 p = c2[i];
                partial += (p.x > key) + (p.y > key);
            }
        }
        s_half[tid] = partial;
        __syncthreads();

        if (tid < (int)count) {
            unsigned int rank = s_half[tid] + s_half[tid + 512];
            if (rank < K_TOP) {
                unsigned long long key = cand[tid];
                unsigned int u   = (unsigned int)(key >> 32);
                unsigned int idx = ~(unsigned int)key;
                const float4* r4 = (const float4*)roi;
                float4 rv = r4[(size_t)row * N_COLS + idx];
                out_score[row * K_TOP + rank] = u2f(u);
                ((float4*)out_roi)[row * K_TOP + rank] = rv;
            }
        }
    } else {
        // ---------- Serial rank (fallback-sized candidate sets only) ----------
        for (int c = tid; c < (int)count; c += TPB) {
            unsigned long long key = cand[c];
            int rank = 0;
            #pragma unroll 8
            for (int i = 0; i < pairs; ++i) {
                ulonglong2 p = c2[i];
                rank += (p.x > key) + (p.y > key);
            }
            if (rank < K_TOP) {
                unsigned int u   = (unsigned int)(key >> 32);
                unsigned int idx = ~(unsigned int)key;
                const float4* r4 = (const float4*)roi;
                float4 rv = r4[(size_t)row * N_COLS + idx];
                out_score[row * K_TOP + rank] = u2f(u);
                ((float4*)out_roi)[row * K_TOP + rank] = rv;
            }
        }
    }
}

extern "C" void kernel_launch(void* const* d_in, const int* in_sizes, int n_in,
                              void* d_out, int out_size) {
    (void)in_sizes; (void)n_in; (void)out_size;
    const float* score = (const float*)d_in[0];
    const float* roi   = (const float*)d_in[1];
    float* out_roi   = (float*)d_out;                               // [128,256,4]
    float* out_score = (float*)d_out + (size_t)B_ROWS * K_TOP * 4;  // [128,256]
    roiselect_kernel<<<B_ROWS, TPB, CAP * sizeof(unsigned long long)>>>(
        score, roi, out_roi, out_score);
}